// round 13
// baseline (speedup 1.0000x reference)
#include <cuda_runtime.h>
#include <cuda_fp16.h>
#include <cstdint>

// ==================== constants ====================
#define BSZ    8192
#define HDIM   1024
#define KTOT   2048           // I + H
#define BTILE  128            // batch rows per CTA
#define HT     32             // h-cols per CTA (per gate)
#define KC     64             // K per chunk (4 x k16 steps)
#define NCHUNK (KTOT / KC)    // 32
#define NTHREADS 256
#define CMOFF  ((size_t)BSZ * HDIM)

// fragment-packed fp16 scratch, uint4 (16B) slots  (same layout as R10)
// A: [bb 64][kc 32][mtg 8][ks 4][lane 32]  = 2M slots (32MB)
// W: [g 4][hb 32][kc 32][ntp 2][ks 4][lane 32] = 1M slots (16MB)
#define A_SLOTS ((size_t)64 * 32 * 8 * 4 * 32)
#define W_SLOTS ((size_t)4 * 32 * 32 * 2 * 4 * 32)
__device__ uint4 g_scr[A_SLOTS + W_SLOTS];

// smem: epilogue gate-exchange only (4 planes of 128x32 f32)
#define SMEM_BYTES 65536

// ==================== helpers ====================
__device__ __forceinline__ void mma_f16(float* d, const uint4& a, uint32_t b0, uint32_t b1) {
    asm volatile(
        "mma.sync.aligned.m16n8k16.row.col.f32.f16.f16.f32 "
        "{%0,%1,%2,%3}, {%4,%5,%6,%7}, {%8,%9}, {%0,%1,%2,%3};"
        : "+f"(d[0]), "+f"(d[1]), "+f"(d[2]), "+f"(d[3])
        : "r"(a.x), "r"(a.y), "r"(a.z), "r"(a.w), "r"(b0), "r"(b1));
}
__device__ __forceinline__ uint32_t h2(float lo, float hi) {
    __half2 v = __floats2half2_rn(lo, hi);
    return *reinterpret_cast<uint32_t*>(&v);
}
__device__ __forceinline__ float sigm(float z) {
    return __fdividef(1.0f, 1.0f + __expf(-z));
}
__device__ __forceinline__ float tanh_(float z) {
    float e = __expf(-2.0f * z);
    return (1.0f - e) * __fdividef(1.0f, 1.0f + e);
}

// ==================== prep: fp16 convert + fragment pack (R10 layout) ====================
__global__ void __launch_bounds__(256) prep_kernel(
    const float* __restrict__ x, const float* __restrict__ h,
    const float* __restrict__ Wxi, const float* __restrict__ Whi,
    const float* __restrict__ Wxf, const float* __restrict__ Whf,
    const float* __restrict__ Wxc, const float* __restrict__ Whc,
    const float* __restrict__ Wxo, const float* __restrict__ Who)
{
    const long t = (long)blockIdx.x * blockDim.x + threadIdx.x;
    if (t < (long)A_SLOTS) {
        const long o = t;
        const int lane = (int)(o & 31);
        const int ks   = (int)((o >> 5) & 3);
        const int mtg  = (int)((o >> 7) & 7);
        const int kc   = (int)((o >> 10) & 31);
        const int bb   = (int)(o >> 15);
        const int gid = lane >> 2, tg = lane & 3;
        const int r0 = bb * 128 + mtg * 16 + gid;
        const int c  = kc * 64 + ks * 16 + 2 * tg;
        const float* S = (c < 1024) ? x : h;
        const int cc = (c < 1024) ? c : c - 1024;
        const float* p0 = S + (size_t)r0 * 1024 + cc;
        const float* p1 = S + (size_t)(r0 + 8) * 1024 + cc;
        uint4 v;
        v.x = h2(p0[0], p0[1]);
        v.y = h2(p1[0], p1[1]);
        v.z = h2(p0[8], p0[9]);
        v.w = h2(p1[8], p1[9]);
        g_scr[o] = v;
    } else if (t < (long)(A_SLOTS + W_SLOTS)) {
        const long o = t - (long)A_SLOTS;
        const int lane = (int)(o & 31);
        const int ks   = (int)((o >> 5) & 3);
        const int ntp  = (int)((o >> 7) & 1);
        const int kc   = (int)((o >> 8) & 31);
        const int hb   = (int)((o >> 13) & 31);
        const int g    = (int)(o >> 18);
        const int gid = lane >> 2, tg = lane & 3;
        const int n_a = hb * 32 + ntp * 16 + gid;
        const int c   = kc * 64 + ks * 16 + 2 * tg;
        const float* wx = (g == 0) ? Wxi : (g == 1) ? Wxf : (g == 2) ? Wxc : Wxo;
        const float* wh = (g == 0) ? Whi : (g == 1) ? Whf : (g == 2) ? Whc : Who;
        const float* S = (c < 1024) ? wx : wh;
        const int cc = (c < 1024) ? c : c - 1024;
        const float* pa = S + (size_t)n_a * 1024 + cc;
        const float* pb = S + (size_t)(n_a + 8) * 1024 + cc;
        uint4 v;
        v.x = h2(pa[0], pa[1]);
        v.y = h2(pa[8], pa[9]);
        v.z = h2(pb[0], pb[1]);
        v.w = h2(pb[8], pb[9]);
        g_scr[A_SLOTS + (size_t)o] = v;
    }
}

// ==================== main fused LSTM: LDG fragments, no smem staging ====================
__global__ void __launch_bounds__(NTHREADS, 2) lstm_fused(
    const float* __restrict__ c_prev,
    const float* __restrict__ bxi, const float* __restrict__ bhi,
    const float* __restrict__ bxf, const float* __restrict__ bhf,
    const float* __restrict__ bxc, const float* __restrict__ bhc,
    const float* __restrict__ bxo, const float* __restrict__ bho,
    float* __restrict__ out)
{
    extern __shared__ float smf[];

    const int tid   = threadIdx.x;
    const int wid   = tid >> 5;
    const int lane  = tid & 31;
    const int gid   = lane >> 2;
    const int tg    = lane & 3;
    const int warp_m = wid >> 2;   // 0..1 (64 rows each)
    const int warp_n = wid & 3;    // 0..3 == gate

    const int hb = blockIdx.x;           // 0..31
    const int bb = blockIdx.y;           // 0..63
    const int h0 = hb * HT;
    const int b0 = bb * BTILE;

    // per-warp fragment base pointers into the packed scratch
    const uint4* __restrict__ Awarp = g_scr
        + (size_t)bb * 32 * 1024                       // [bb][kc=0]
        + (size_t)(warp_m * 4) * 128 + lane;           // [mtg = warp_m*4][ks=0][lane]
    const uint4* __restrict__ Wwarp = g_scr + A_SLOTS
        + ((size_t)warp_n * 32 + hb) * 32 * 256 + lane;  // [g=warp_n][hb][kc=0][ntp=0][ks=0][lane]

    float acc[4][4][4];
    #pragma unroll
    for (int a = 0; a < 4; a++)
        #pragma unroll
        for (int b = 0; b < 4; b++)
            #pragma unroll
            for (int c = 0; c < 4; c++) acc[a][b][c] = 0.0f;

    for (int kc = 0; kc < NCHUNK; kc++) {
        const uint4* __restrict__ Ak = Awarp + (size_t)kc * 1024;
        const uint4* __restrict__ Wk = Wwarp + (size_t)kc * 256;

        #pragma unroll
        for (int ks = 0; ks < 4; ks++) {
            uint4 av[4], bv[2];
            #pragma unroll
            for (int mt = 0; mt < 4; mt++)
                av[mt] = Ak[(mt * 4 + ks) * 32];
            #pragma unroll
            for (int ntp = 0; ntp < 2; ntp++)
                bv[ntp] = Wk[(ntp * 4 + ks) * 32];
            #pragma unroll
            for (int mt = 0; mt < 4; mt++) {
                #pragma unroll
                for (int ntp = 0; ntp < 2; ntp++) {
                    mma_f16(acc[mt][2 * ntp],     av[mt], bv[ntp].x, bv[ntp].y);
                    mma_f16(acc[mt][2 * ntp + 1], av[mt], bv[ntp].z, bv[ntp].w);
                }
            }
        }
        // keep warps converged so shared lines stay hot in L1
        __syncthreads();
    }

    // ---------- epilogue: gate exchange through smem ----------
    {
        float* ep = smf + warp_n * 4096;   // plane [128][32]
        #pragma unroll
        for (int mt = 0; mt < 4; mt++) {
            #pragma unroll
            for (int nt = 0; nt < 4; nt++) {
                const int r = warp_m * 64 + mt * 16 + gid;
                const int c = nt * 8 + 2 * tg;
                *(float2*)(ep + r * 32 + c)       = make_float2(acc[mt][nt][0], acc[mt][nt][1]);
                *(float2*)(ep + (r + 8) * 32 + c) = make_float2(acc[mt][nt][2], acc[mt][nt][3]);
            }
        }
    }
    __syncthreads();

    {
        const int col = tid & 31;
        const int grp = tid >> 5;
        const int h   = h0 + col;
        const float bi  = bxi[h] + bhi[h];
        const float bfv = bxf[h] + bhf[h];
        const float bc  = bxc[h] + bhc[h];
        const float bo  = bxo[h] + bho[h];
        const float* ep = smf;

        #pragma unroll
        for (int j = 0; j < 16; j++) {
            const int r  = grp * 16 + j;
            const int gb = b0 + r;
            const int o_ = r * 32 + col;
            const float zi = ep[o_]         + bi;
            const float zf = ep[4096 + o_]  + bfv;
            const float zc = ep[8192 + o_]  + bc;
            const float zo = ep[12288 + o_] + bo;
            const float iv = sigm(zi), fv = sigm(zf);
            const float gv = tanh_(zc), ov = sigm(zo);
            const float cp = c_prev[(size_t)gb * 1024 + h];
            const float cn = fv * cp + iv * gv;
            out[(size_t)gb * 1024 + h]         = ov * tanh_(cn);
            out[CMOFF + (size_t)gb * 1024 + h] = cn;
        }
    }
}

// ==================== launch ====================
extern "C" void kernel_launch(void* const* d_in, const int* in_sizes, int n_in,
                              void* d_out, int out_size) {
    const float* x      = (const float*)d_in[0];
    const float* h_prev = (const float*)d_in[1];
    const float* c_prev = (const float*)d_in[2];
    const float* Wxi = (const float*)d_in[3];
    const float* Whi = (const float*)d_in[4];
    const float* Wxf = (const float*)d_in[5];
    const float* Whf = (const float*)d_in[6];
    const float* Wxc = (const float*)d_in[7];
    const float* Whc = (const float*)d_in[8];
    const float* Wxo = (const float*)d_in[9];
    const float* Who = (const float*)d_in[10];
    const float* bxi = (const float*)d_in[11];
    const float* bhi = (const float*)d_in[12];
    const float* bxf = (const float*)d_in[13];
    const float* bhf = (const float*)d_in[14];
    const float* bxc = (const float*)d_in[15];
    const float* bhc = (const float*)d_in[16];
    const float* bxo = (const float*)d_in[17];
    const float* bho = (const float*)d_in[18];
    float* out = (float*)d_out;

    cudaFuncSetAttribute(lstm_fused, cudaFuncAttributeMaxDynamicSharedMemorySize, SMEM_BYTES);

    const long total = (long)(A_SLOTS + W_SLOTS);   // 3M threads
    prep_kernel<<<(unsigned)((total + 255) / 256), 256>>>(x, h_prev,
        Wxi, Whi, Wxf, Whf, Wxc, Whc, Wxo, Who);

    dim3 grid(HDIM / HT, BSZ / BTILE);   // (32, 64) = 2048 CTAs
    lstm_fused<<<grid, NTHREADS, SMEM_BYTES>>>(
        c_prev,
        bxi, bhi, bxf, bhf, bxc, bhc, bxo, bho,
        out);
}

// round 14
// speedup vs baseline: 1.0997x; 1.0997x over previous
#include <cuda_runtime.h>
#include <cuda_fp16.h>
#include <cstdint>

// ==================== constants ====================
#define BSZ    8192
#define HDIM   1024
#define KTOT   2048           // I + H
#define BTILE  128            // batch rows per CTA
#define HT     32             // h-cols per CTA (per gate)
#define KC     64             // K per chunk (4 x k16 steps)
#define NCHUNK (KTOT / KC)    // 32
#define NTHREADS 256
#define CMOFF  ((size_t)BSZ * HDIM)

// fragment-packed fp16 scratch, uint4 (16B) slots  (R10 layout)
// A: [bb 64][kc 32][mtg 8][ks 4][lane 32]  = 2M slots (32MB)
// W: [g 4][hb 32][kc 32][ntp 2][ks 4][lane 32] = 1M slots (16MB)
#define A_SLOTS ((size_t)64 * 32 * 8 * 4 * 32)
#define W_SLOTS ((size_t)4 * 32 * 32 * 2 * 4 * 32)
__device__ uint4 g_scr[A_SLOTS + W_SLOTS];

// smem: epilogue gate-exchange only (4 planes of 128x32 f32)
#define SMEM_BYTES 65536

// ==================== helpers ====================
__device__ __forceinline__ void mma_f16(float* d, const uint4& a, uint32_t b0, uint32_t b1) {
    asm volatile(
        "mma.sync.aligned.m16n8k16.row.col.f32.f16.f16.f32 "
        "{%0,%1,%2,%3}, {%4,%5,%6,%7}, {%8,%9}, {%0,%1,%2,%3};"
        : "+f"(d[0]), "+f"(d[1]), "+f"(d[2]), "+f"(d[3])
        : "r"(a.x), "r"(a.y), "r"(a.z), "r"(a.w), "r"(b0), "r"(b1));
}
__device__ __forceinline__ uint32_t h2(float lo, float hi) {
    __half2 v = __floats2half2_rn(lo, hi);
    return *reinterpret_cast<uint32_t*>(&v);
}
__device__ __forceinline__ float sigm(float z) {
    return __fdividef(1.0f, 1.0f + __expf(-z));
}
__device__ __forceinline__ float tanh_(float z) {
    float e = __expf(-2.0f * z);
    return (1.0f - e) * __fdividef(1.0f, 1.0f + e);
}

// ==================== prep: fp16 convert + fragment pack (R10 layout) ====================
__global__ void __launch_bounds__(256) prep_kernel(
    const float* __restrict__ x, const float* __restrict__ h,
    const float* __restrict__ Wxi, const float* __restrict__ Whi,
    const float* __restrict__ Wxf, const float* __restrict__ Whf,
    const float* __restrict__ Wxc, const float* __restrict__ Whc,
    const float* __restrict__ Wxo, const float* __restrict__ Who)
{
    const long t = (long)blockIdx.x * blockDim.x + threadIdx.x;
    if (t < (long)A_SLOTS) {
        const long o = t;
        const int lane = (int)(o & 31);
        const int ks   = (int)((o >> 5) & 3);
        const int mtg  = (int)((o >> 7) & 7);
        const int kc   = (int)((o >> 10) & 31);
        const int bb   = (int)(o >> 15);
        const int gid = lane >> 2, tg = lane & 3;
        const int r0 = bb * 128 + mtg * 16 + gid;
        const int c  = kc * 64 + ks * 16 + 2 * tg;
        const float* S = (c < 1024) ? x : h;
        const int cc = (c < 1024) ? c : c - 1024;
        const float* p0 = S + (size_t)r0 * 1024 + cc;
        const float* p1 = S + (size_t)(r0 + 8) * 1024 + cc;
        uint4 v;
        v.x = h2(p0[0], p0[1]);
        v.y = h2(p1[0], p1[1]);
        v.z = h2(p0[8], p0[9]);
        v.w = h2(p1[8], p1[9]);
        g_scr[o] = v;
    } else if (t < (long)(A_SLOTS + W_SLOTS)) {
        const long o = t - (long)A_SLOTS;
        const int lane = (int)(o & 31);
        const int ks   = (int)((o >> 5) & 3);
        const int ntp  = (int)((o >> 7) & 1);
        const int kc   = (int)((o >> 8) & 31);
        const int hb   = (int)((o >> 13) & 31);
        const int g    = (int)(o >> 18);
        const int gid = lane >> 2, tg = lane & 3;
        const int n_a = hb * 32 + ntp * 16 + gid;
        const int c   = kc * 64 + ks * 16 + 2 * tg;
        const float* wx = (g == 0) ? Wxi : (g == 1) ? Wxf : (g == 2) ? Wxc : Wxo;
        const float* wh = (g == 0) ? Whi : (g == 1) ? Whf : (g == 2) ? Whc : Who;
        const float* S = (c < 1024) ? wx : wh;
        const int cc = (c < 1024) ? c : c - 1024;
        const float* pa = S + (size_t)n_a * 1024 + cc;
        const float* pb = S + (size_t)(n_a + 8) * 1024 + cc;
        uint4 v;
        v.x = h2(pa[0], pa[1]);
        v.y = h2(pa[8], pa[9]);
        v.z = h2(pb[0], pb[1]);
        v.w = h2(pb[8], pb[9]);
        g_scr[A_SLOTS + (size_t)o] = v;
    }
}

// ==================== main fused LSTM: free-running LDG fragments, zero mainloop sync ====================
__global__ void __launch_bounds__(NTHREADS, 2) lstm_fused(
    const float* __restrict__ c_prev,
    const float* __restrict__ bxi, const float* __restrict__ bhi,
    const float* __restrict__ bxf, const float* __restrict__ bhf,
    const float* __restrict__ bxc, const float* __restrict__ bhc,
    const float* __restrict__ bxo, const float* __restrict__ bho,
    float* __restrict__ out)
{
    extern __shared__ float smf[];

    const int tid   = threadIdx.x;
    const int wid   = tid >> 5;
    const int lane  = tid & 31;
    const int gid   = lane >> 2;
    const int tg    = lane & 3;
    const int warp_m = wid >> 2;   // 0..1 (64 rows each)
    const int warp_n = wid & 3;    // 0..3 == gate

    const int hb = blockIdx.x;           // 0..31
    const int bb = blockIdx.y;           // 0..63
    const int h0 = hb * HT;
    const int b0 = bb * BTILE;

    // per-warp fragment base pointers into the packed scratch
    const uint4* __restrict__ Awarp = g_scr
        + (size_t)bb * 32 * 1024
        + (size_t)(warp_m * 4) * 128 + lane;
    const uint4* __restrict__ Wwarp = g_scr + A_SLOTS
        + ((size_t)warp_n * 32 + hb) * 32 * 256 + lane;

    float acc[4][4][4];
    #pragma unroll
    for (int a = 0; a < 4; a++)
        #pragma unroll
        for (int b = 0; b < 4; b++)
            #pragma unroll
            for (int c = 0; c < 4; c++) acc[a][b][c] = 0.0f;

    #pragma unroll 2
    for (int kc = 0; kc < NCHUNK; kc++) {
        const uint4* __restrict__ Ak = Awarp + (size_t)kc * 1024;
        const uint4* __restrict__ Wk = Wwarp + (size_t)kc * 256;

        #pragma unroll
        for (int ks = 0; ks < 4; ks++) {
            uint4 av[4], bv[2];
            #pragma unroll
            for (int mt = 0; mt < 4; mt++)
                av[mt] = Ak[(mt * 4 + ks) * 32];
            #pragma unroll
            for (int ntp = 0; ntp < 2; ntp++)
                bv[ntp] = Wk[(ntp * 4 + ks) * 32];
            #pragma unroll
            for (int mt = 0; mt < 4; mt++) {
                #pragma unroll
                for (int ntp = 0; ntp < 2; ntp++) {
                    mma_f16(acc[mt][2 * ntp],     av[mt], bv[ntp].x, bv[ntp].y);
                    mma_f16(acc[mt][2 * ntp + 1], av[mt], bv[ntp].z, bv[ntp].w);
                }
            }
        }
        // no synchronization: warps free-run; scoreboard covers L1/L2 latency
    }

    // ---------- epilogue: gate exchange through smem ----------
    {
        float* ep = smf + warp_n * 4096;   // plane [128][32]
        #pragma unroll
        for (int mt = 0; mt < 4; mt++) {
            #pragma unroll
            for (int nt = 0; nt < 4; nt++) {
                const int r = warp_m * 64 + mt * 16 + gid;
                const int c = nt * 8 + 2 * tg;
                *(float2*)(ep + r * 32 + c)       = make_float2(acc[mt][nt][0], acc[mt][nt][1]);
                *(float2*)(ep + (r + 8) * 32 + c) = make_float2(acc[mt][nt][2], acc[mt][nt][3]);
            }
        }
    }
    __syncthreads();

    {
        const int col = tid & 31;
        const int grp = tid >> 5;
        const int h   = h0 + col;
        const float bi  = bxi[h] + bhi[h];
        const float bfv = bxf[h] + bhf[h];
        const float bc  = bxc[h] + bhc[h];
        const float bo  = bxo[h] + bho[h];
        const float* ep = smf;

        #pragma unroll
        for (int j = 0; j < 16; j++) {
            const int r  = grp * 16 + j;
            const int gb = b0 + r;
            const int o_ = r * 32 + col;
            const float zi = ep[o_]         + bi;
            const float zf = ep[4096 + o_]  + bfv;
            const float zc = ep[8192 + o_]  + bc;
            const float zo = ep[12288 + o_] + bo;
            const float iv = sigm(zi), fv = sigm(zf);
            const float gv = tanh_(zc), ov = sigm(zo);
            const float cp = c_prev[(size_t)gb * 1024 + h];
            const float cn = fv * cp + iv * gv;
            out[(size_t)gb * 1024 + h]         = ov * tanh_(cn);
            out[CMOFF + (size_t)gb * 1024 + h] = cn;
        }
    }
}

// ==================== launch ====================
extern "C" void kernel_launch(void* const* d_in, const int* in_sizes, int n_in,
                              void* d_out, int out_size) {
    const float* x      = (const float*)d_in[0];
    const float* h_prev = (const float*)d_in[1];
    const float* c_prev = (const float*)d_in[2];
    const float* Wxi = (const float*)d_in[3];
    const float* Whi = (const float*)d_in[4];
    const float* Wxf = (const float*)d_in[5];
    const float* Whf = (const float*)d_in[6];
    const float* Wxc = (const float*)d_in[7];
    const float* Whc = (const float*)d_in[8];
    const float* Wxo = (const float*)d_in[9];
    const float* Who = (const float*)d_in[10];
    const float* bxi = (const float*)d_in[11];
    const float* bhi = (const float*)d_in[12];
    const float* bxf = (const float*)d_in[13];
    const float* bhf = (const float*)d_in[14];
    const float* bxc = (const float*)d_in[15];
    const float* bhc = (const float*)d_in[16];
    const float* bxo = (const float*)d_in[17];
    const float* bho = (const float*)d_in[18];
    float* out = (float*)d_out;

    cudaFuncSetAttribute(lstm_fused, cudaFuncAttributeMaxDynamicSharedMemorySize, SMEM_BYTES);

    const long total = (long)(A_SLOTS + W_SLOTS);   // 3M threads
    prep_kernel<<<(unsigned)((total + 255) / 256), 256>>>(x, h_prev,
        Wxi, Whi, Wxf, Whf, Wxc, Whc, Wxo, Who);

    dim3 grid(HDIM / HT, BSZ / BTILE);   // (32, 64) = 2048 CTAs
    lstm_fused<<<grid, NTHREADS, SMEM_BYTES>>>(
        c_prev,
        bxi, bhi, bxf, bhf, bxc, bhc, bxo, bho,
        out);
}